// round 1
// baseline (speedup 1.0000x reference)
#include <cuda_runtime.h>

// Problem constants
#define BB 4
#define SS 384
#define DD 300
#define EE 50
#define HH 150          // HD
#define BSR (BB*SS)     // 1536 rows flattened
#define D1 (DD+HH)      // 450
#define WHC (2*HH+EE)   // 350 (Wh column count)

// ---------------- device scratch (static, no runtime alloc) ----------------
__device__ float g_we[EE];
__device__ float g_w1s[HH];
__device__ float g_w2s[HH];
__device__ float g_sbh[1];
__device__ float g_A0[BB*SS*SS];
__device__ float g_A1[BB*SS*SS];
__device__ float g_Y0[BSR*DD];
__device__ float g_g0[BSR*HH];
__device__ float g_out1[BSR*D1];
__device__ float g_s1[BSR];
__device__ float g_s2[BSR];
__device__ float g_T[BB*D1];
__device__ float g_u[BB*D1];
__device__ float g_Y1[BSR*D1];
__device__ float g_g1[BSR*HH];
__device__ float g_Z[BSR*DD];

// ---------------- weight prep: column sums of Wh splits, sum(bh) ----------
__global__ void prep_weights(const float* __restrict__ Wh, const float* __restrict__ bh) {
    int t = threadIdx.x;
    if (t < EE) {
        float s = 0.f;
        for (int f = 0; f < EE; f++) s += Wh[f*WHC + t];
        g_we[t] = s;
    }
    if (t < HH) {
        float s1 = 0.f, s2 = 0.f;
        for (int f = 0; f < EE; f++) {
            s1 += Wh[f*WHC + EE + t];
            s2 += Wh[f*WHC + EE + HH + t];
        }
        g_w1s[t] = s1;
        g_w2s[t] = s2;
    }
    if (t == 0) {
        float s = 0.f;
        for (int e = 0; e < EE; e++) s += bh[e];
        g_sbh[0] = s;
    }
}

// ---------------- adj reduction: A0 = sum_e adj, A1 = sum_e adj*we --------
// One warp per (b,i,k) row of 50 floats (200B). 25 lanes do float2 loads.
__global__ void adj_reduce(const float* __restrict__ adj) {
    long long warp = (long long)(blockIdx.x) * (blockDim.x >> 5) + (threadIdx.x >> 5);
    int lane = threadIdx.x & 31;
    const long long nrows = (long long)BB * SS * SS;
    if (warp >= nrows) return;
    const float2* p = (const float2*)(adj + warp * EE);
    float s0 = 0.f, s1 = 0.f;
    if (lane < 25) {
        float2 v = p[lane];
        s0 = v.x + v.y;
        s1 = v.x * g_we[2*lane] + v.y * g_we[2*lane + 1];
    }
    #pragma unroll
    for (int o = 16; o > 0; o >>= 1) {
        s0 += __shfl_down_sync(0xffffffffu, s0, o);
        s1 += __shfl_down_sync(0xffffffffu, s1, o);
    }
    if (lane == 0) {
        g_A0[warp] = s0;
        g_A1[warp] = s1;
    }
}

// ---------------- NN GEMM for layer 0: Y0 = A0@X/E + X ---------------------
// Per batch: A0[b] (S,S) rm, X[b] (S,D) rm. BM=BN=64, BK=16, 4x4 per thread.
__global__ void gemm_y0(const float* __restrict__ X) {
    __shared__ float As[16][68];
    __shared__ float Bs[16][68];
    int b = blockIdx.z;
    const float* A  = g_A0 + (long long)b * SS * SS;
    const float* Bm = X + (long long)b * SS * DD;
    int row0 = blockIdx.y * 64, col0 = blockIdx.x * 64;
    int tid = threadIdx.x, tx = tid & 15, ty = tid >> 4;
    int ak = tid & 15, am = tid >> 4;   // A loads: k fast
    int bn = tid & 63, bk = tid >> 6;   // B loads: n fast
    float acc[4][4] = {};
    for (int k0 = 0; k0 < SS; k0 += 16) {
        #pragma unroll
        for (int mm = 0; mm < 4; mm++) {
            int m = am + mm * 16;
            As[ak][m] = A[(row0 + m) * SS + k0 + ak];
        }
        #pragma unroll
        for (int kk = 0; kk < 4; kk++) {
            int k = bk + kk * 4;
            int n = col0 + bn;
            Bs[k][bn] = (n < DD) ? Bm[(k0 + k) * DD + n] : 0.f;
        }
        __syncthreads();
        #pragma unroll
        for (int kk = 0; kk < 16; kk++) {
            float4 av = *(const float4*)&As[kk][ty * 4];
            float4 bv = *(const float4*)&Bs[kk][tx * 4];
            float ar[4] = {av.x, av.y, av.z, av.w};
            float br[4] = {bv.x, bv.y, bv.z, bv.w};
            #pragma unroll
            for (int i = 0; i < 4; i++)
                #pragma unroll
                for (int j = 0; j < 4; j++)
                    acc[i][j] = fmaf(ar[i], br[j], acc[i][j]);
        }
        __syncthreads();
    }
    #pragma unroll
    for (int i = 0; i < 4; i++) {
        int mg = b * SS + row0 + ty * 4 + i;
        #pragma unroll
        for (int j = 0; j < 4; j++) {
            int n = col0 + tx * 4 + j;
            if (n < DD)
                g_Y0[mg * DD + n] = acc[i][j] * (1.f / EE) + X[mg * DD + n];
        }
    }
}

// ---------------- build out1 = concat(X, g0) -------------------------------
__global__ void build_out1(const float* __restrict__ X) {
    int idx = blockIdx.x * blockDim.x + threadIdx.x;
    if (idx >= BSR * D1) return;
    int r = idx / D1, d = idx % D1;
    g_out1[idx] = (d < DD) ? X[r * DD + d] : g_g0[r * HH + (d - DD)];
}

// ---------------- s1[b,s] = g0.w1s ; s2 = g0.w2s (warp per row) ------------
__global__ void s_kernel() {
    int warp = (blockIdx.x * blockDim.x + threadIdx.x) >> 5;
    int lane = threadIdx.x & 31;
    if (warp >= BSR) return;
    const float* g = g_g0 + warp * HH;
    float a = 0.f, b2 = 0.f;
    for (int j = lane; j < HH; j += 32) {
        float v = g[j];
        a  += v * g_w1s[j];
        b2 += v * g_w2s[j];
    }
    #pragma unroll
    for (int o = 16; o > 0; o >>= 1) {
        a  += __shfl_down_sync(0xffffffffu, a, o);
        b2 += __shfl_down_sync(0xffffffffu, b2, o);
    }
    if (lane == 0) { g_s1[warp] = a; g_s2[warp] = b2; }
}

// ---------------- column sums: T[b,d] = sum_k out1 ; u = sum_k s1*out1 -----
__global__ void colsum_kernel() {
    int b = blockIdx.y;
    int d = blockIdx.x * blockDim.x + threadIdx.x;
    if (d >= D1) return;
    const float* o  = g_out1 + (long long)b * SS * D1;
    const float* s1 = g_s1 + b * SS;
    float T = 0.f, u = 0.f;
    for (int k = 0; k < SS; k++) {
        float v = o[k * D1 + d];
        T += v;
        u = fmaf(s1[k], v, u);
    }
    g_T[b * D1 + d] = T;
    g_u[b * D1 + d] = u;
}

// ---------------- NN GEMM layer 1: Y1 = (A1@out1 + u + (s2+sbh)T)/E + out1 -
__global__ void gemm_y1() {
    __shared__ float As[16][68];
    __shared__ float Bs[16][68];
    int b = blockIdx.z;
    const float* A  = g_A1 + (long long)b * SS * SS;
    const float* Bm = g_out1 + (long long)b * SS * D1;
    int row0 = blockIdx.y * 64, col0 = blockIdx.x * 64;
    int tid = threadIdx.x, tx = tid & 15, ty = tid >> 4;
    int ak = tid & 15, am = tid >> 4;
    int bn = tid & 63, bk = tid >> 6;
    float acc[4][4] = {};
    for (int k0 = 0; k0 < SS; k0 += 16) {
        #pragma unroll
        for (int mm = 0; mm < 4; mm++) {
            int m = am + mm * 16;
            As[ak][m] = A[(row0 + m) * SS + k0 + ak];
        }
        #pragma unroll
        for (int kk = 0; kk < 4; kk++) {
            int k = bk + kk * 4;
            int n = col0 + bn;
            Bs[k][bn] = (n < D1) ? Bm[(k0 + k) * D1 + n] : 0.f;
        }
        __syncthreads();
        #pragma unroll
        for (int kk = 0; kk < 16; kk++) {
            float4 av = *(const float4*)&As[kk][ty * 4];
            float4 bv = *(const float4*)&Bs[kk][tx * 4];
            float ar[4] = {av.x, av.y, av.z, av.w};
            float br[4] = {bv.x, bv.y, bv.z, bv.w};
            #pragma unroll
            for (int i = 0; i < 4; i++)
                #pragma unroll
                for (int j = 0; j < 4; j++)
                    acc[i][j] = fmaf(ar[i], br[j], acc[i][j]);
        }
        __syncthreads();
    }
    float sbh = g_sbh[0];
    #pragma unroll
    for (int i = 0; i < 4; i++) {
        int mg = b * SS + row0 + ty * 4 + i;
        float s2v = g_s2[mg] + sbh;
        #pragma unroll
        for (int j = 0; j < 4; j++) {
            int n = col0 + tx * 4 + j;
            if (n < D1) {
                float ax = (acc[i][j] + g_u[b * D1 + n] + s2v * g_T[b * D1 + n]) * (1.f / EE);
                g_Y1[mg * D1 + n] = ax + g_out1[mg * D1 + n];
            }
        }
    }
}

// ---------------- build Z = X + concat(g0, g1) -----------------------------
__global__ void build_z(const float* __restrict__ X) {
    int idx = blockIdx.x * blockDim.x + threadIdx.x;
    if (idx >= BSR * DD) return;
    int r = idx / DD, d = idx % DD;
    float v = (d < HH) ? g_g0[r * HH + d] : g_g1[r * HH + (d - HH)];
    g_Z[idx] = X[idx] + v;
}

// ---------------- NT GEMM: C = A @ W^T + bscale*bias (optional relu) -------
// mode 0: A=g_Y0, C=g_g0 (relu, bscale=2)     M=1536,N=150,K=300
// mode 1: A=g_Y1, C=g_g1 (relu, bscale=2)     M=1536,N=150,K=450
// mode 2: A=g_Z,  C=Cout (no relu, bscale=1)  M=1536,N=300,K=300
__global__ void gemm_nt(const float* __restrict__ W, const float* __restrict__ bias,
                        float bscale, float* __restrict__ Cout,
                        int N, int K, int relu, int mode) {
    const float* A = (mode == 0) ? g_Y0 : (mode == 1) ? g_Y1 : g_Z;
    float* C = (mode == 0) ? g_g0 : (mode == 1) ? g_g1 : Cout;
    __shared__ float As[16][68];
    __shared__ float Ws[16][68];
    int row0 = blockIdx.y * 64, col0 = blockIdx.x * 64;
    int tid = threadIdx.x, tx = tid & 15, ty = tid >> 4;
    int lk = tid & 15, lm = tid >> 4;
    float acc[4][4] = {};
    for (int k0 = 0; k0 < K; k0 += 16) {
        int k = k0 + lk;
        bool kok = (k < K);
        #pragma unroll
        for (int mm = 0; mm < 4; mm++) {
            int m = lm + mm * 16;
            As[lk][m] = kok ? A[(row0 + m) * K + k] : 0.f;
        }
        #pragma unroll
        for (int nn = 0; nn < 4; nn++) {
            int n = lm + nn * 16;
            int gn = col0 + n;
            Ws[lk][n] = (kok && gn < N) ? W[gn * K + k] : 0.f;
        }
        __syncthreads();
        #pragma unroll
        for (int kk = 0; kk < 16; kk++) {
            float4 av = *(const float4*)&As[kk][ty * 4];
            float4 wv = *(const float4*)&Ws[kk][tx * 4];
            float ar[4] = {av.x, av.y, av.z, av.w};
            float wr[4] = {wv.x, wv.y, wv.z, wv.w};
            #pragma unroll
            for (int i = 0; i < 4; i++)
                #pragma unroll
                for (int j = 0; j < 4; j++)
                    acc[i][j] = fmaf(ar[i], wr[j], acc[i][j]);
        }
        __syncthreads();
    }
    #pragma unroll
    for (int i = 0; i < 4; i++) {
        int m = row0 + ty * 4 + i;
        #pragma unroll
        for (int j = 0; j < 4; j++) {
            int n = col0 + tx * 4 + j;
            if (n < N) {
                float v = acc[i][j] + bscale * bias[n];
                if (relu) v = fmaxf(v, 0.f);
                C[m * N + n] = v;
            }
        }
    }
}

// ---------------- launch ----------------------------------------------------
extern "C" void kernel_launch(void* const* d_in, const int* in_sizes, int n_in,
                              void* d_out, int out_size) {
    const float* adj  = (const float*)d_in[0];
    const float* X    = (const float*)d_in[1];
    const float* W0   = (const float*)d_in[2];
    const float* b0   = (const float*)d_in[3];
    const float* W1   = (const float*)d_in[4];
    const float* b1   = (const float*)d_in[5];
    const float* Wh   = (const float*)d_in[6];
    const float* bh   = (const float*)d_in[7];
    const float* Wout = (const float*)d_in[8];
    const float* bout = (const float*)d_in[9];
    float* out = (float*)d_out;

    // 1. weight column sums
    prep_weights<<<1, 256>>>(Wh, bh);

    // 2. single streaming pass over adj (118 MB): A0, A1
    {
        const int nrows = BB * SS * SS;     // 589824 rows, one warp each
        const int wpb = 8;                  // 8 warps per 256-thread block
        adj_reduce<<<(nrows + wpb - 1) / wpb, 256>>>(adj);
    }

    // 3. layer 0: Y0 = A0@X/E + X
    gemm_y0<<<dim3((DD + 63) / 64, SS / 64, BB), 256>>>(X);

    // 4. g0 = relu(Y0 @ W0^T + 2*b0)
    gemm_nt<<<dim3((HH + 63) / 64, BSR / 64), 256>>>(W0, b0, 2.f, nullptr, HH, DD, 1, 0);

    // 5. out1 = concat(X, g0); s1/s2; column sums T, u
    build_out1<<<(BSR * D1 + 255) / 256, 256>>>(X);
    s_kernel<<<(BSR * 32 + 255) / 256, 256>>>();
    colsum_kernel<<<dim3((D1 + 127) / 128, BB), 128>>>();

    // 6. layer 1: Y1 = (A1@out1 + u + (s2+sbh)*T)/E + out1
    gemm_y1<<<dim3((D1 + 63) / 64, SS / 64, BB), 256>>>();

    // 7. g1 = relu(Y1 @ W1^T + 2*b1)
    gemm_nt<<<dim3((HH + 63) / 64, BSR / 64), 256>>>(W1, b1, 2.f, nullptr, HH, D1, 1, 1);

    // 8. Z = X + concat(g0, g1); out = Z @ Wout^T + bout
    build_z<<<(BSR * DD + 255) / 256, 256>>>(X);
    gemm_nt<<<dim3((DD + 63) / 64, BSR / 64), 256>>>(Wout, bout, 1.f, out, DD, DD, 0, 2);
}

// round 2
// speedup vs baseline: 1.0876x; 1.0876x over previous
#include <cuda_runtime.h>

#define BBATCH 4
#define SSZ 384
#define DD 300
#define EE 50
#define HH 150
#define BSR (BBATCH*SSZ)   /* 1536 */
#define D1 450

// ---------------- device scratch ----------------
__device__ float g_we[EE];
__device__ float g_w1s[HH];
__device__ float g_w2s[HH];
__device__ float g_sbh;
__device__ float g_A0[BBATCH*SSZ*SSZ];
__device__ float g_A1[BBATCH*SSZ*SSZ];
__device__ float g_Q [BSR*HH];
__device__ float g_S0[BSR*HH];   // pre-relu layer0 activation
__device__ float g_P [BSR*HH];
__device__ float g_s1[BSR];
__device__ float g_s2[BSR];
__device__ float g_Tp[BBATCH*HH];
__device__ float g_up[BBATCH*HH];
__device__ float g_S1[BSR*HH];   // pre-relu layer1 activation

// ---------------- prep: column sums of Wh splits, sum(bh) ------------------
__global__ void prep_weights(const float* __restrict__ Wh, const float* __restrict__ bh) {
    int t = threadIdx.x;
    const int WHC = 2*HH + EE;
    if (t < EE) {
        float s = 0.f;
        for (int f = 0; f < EE; f++) s += Wh[f*WHC + t];
        g_we[t] = s;
    }
    if (t < HH) {
        float a = 0.f, b = 0.f;
        for (int f = 0; f < EE; f++) {
            a += Wh[f*WHC + EE + t];
            b += Wh[f*WHC + EE + HH + t];
        }
        g_w1s[t] = a;
        g_w2s[t] = b;
    }
    if (t == 0) {
        float s = 0.f;
        for (int e = 0; e < EE; e++) s += bh[e];
        g_sbh = s;
    }
}

// ======================= NT GEMM core (C = A@W^T) ===========================
// BM=64, BN=32, BK=16, 128 threads, 4x4 per thread, register prefetch.
// MODE 0: A = X (K=300), C = g_Q, no bias
// MODE 1: A = [X | relu(S0)] (K=450), C = g_P, no bias
// MODE 2: A = X + relu([S0|S1]) (K=300), C = d_out, +bias
template<int MODE>
__device__ __forceinline__ float loadA_nt(const float* __restrict__ X, int m, int k) {
    if (MODE == 0) return X[m*DD + k];
    if (MODE == 1) {
        if (k < DD) return X[m*DD + k];
        return fmaxf(g_S0[m*HH + (k - DD)], 0.f);
    }
    // MODE 2
    float s = (k < HH) ? g_S0[m*HH + k] : g_S1[m*HH + (k - HH)];
    return X[m*DD + k] + fmaxf(s, 0.f);
}

template<int MODE, int KDIM, int NDIM>
__device__ __forceinline__ void nt_core(int bx, const float* __restrict__ X,
                                        const float* __restrict__ W,
                                        const float* __restrict__ bias,
                                        float* __restrict__ C) {
    __shared__ float As[16][68];
    __shared__ float Ws[16][36];
    const int BN_TILES = (NDIM + 31) / 32;
    int m0 = (bx / BN_TILES) * 64;
    int n0 = (bx % BN_TILES) * 32;
    int tid = threadIdx.x;
    int lk = tid & 15, lm = tid >> 4;      // loaders
    int tx = tid & 7,  ty = tid >> 3;      // compute grid
    const int NIT = (KDIM + 15) / 16;

    float ar[8], br[4];
    float acc[4][4] = {};

    // prefetch iter 0
    {
        int k = lk;
        bool kok = (k < KDIM);
        #pragma unroll
        for (int mm = 0; mm < 8; mm++)
            ar[mm] = kok ? loadA_nt<MODE>(X, m0 + lm*8 + mm, k) : 0.f;
        #pragma unroll
        for (int nn = 0; nn < 4; nn++) {
            int n = n0 + lm*4 + nn;
            br[nn] = (kok && n < NDIM) ? W[n*KDIM + k] : 0.f;
        }
    }

    for (int it = 0; it < NIT; it++) {
        __syncthreads();
        #pragma unroll
        for (int mm = 0; mm < 8; mm++) As[lk][lm*8 + mm] = ar[mm];
        #pragma unroll
        for (int nn = 0; nn < 4; nn++) Ws[lk][lm*4 + nn] = br[nn];
        __syncthreads();

        if (it + 1 < NIT) {
            int k = (it + 1) * 16 + lk;
            bool kok = (k < KDIM);
            #pragma unroll
            for (int mm = 0; mm < 8; mm++)
                ar[mm] = kok ? loadA_nt<MODE>(X, m0 + lm*8 + mm, k) : 0.f;
            #pragma unroll
            for (int nn = 0; nn < 4; nn++) {
                int n = n0 + lm*4 + nn;
                br[nn] = (kok && n < NDIM) ? W[n*KDIM + k] : 0.f;
            }
        }

        #pragma unroll
        for (int kk = 0; kk < 16; kk++) {
            float4 av = *(const float4*)&As[kk][ty*4];
            float4 bv = *(const float4*)&Ws[kk][tx*4];
            float a[4] = {av.x, av.y, av.z, av.w};
            float b[4] = {bv.x, bv.y, bv.z, bv.w};
            #pragma unroll
            for (int i = 0; i < 4; i++)
                #pragma unroll
                for (int j = 0; j < 4; j++)
                    acc[i][j] = fmaf(a[i], b[j], acc[i][j]);
        }
    }

    #pragma unroll
    for (int i = 0; i < 4; i++) {
        int m = m0 + ty*4 + i;
        #pragma unroll
        for (int j = 0; j < 4; j++) {
            int n = n0 + tx*4 + j;
            if (n < NDIM) {
                float v = acc[i][j];
                if (MODE == 2) v += bias[n];
                C[m*NDIM + n] = v;
            }
        }
    }
}

// ======================= stage1: Q GEMM + adj reduction =====================
#define NQ_BLOCKS 120                 /* 24 m-tiles x 5 n-tiles */
#define ADJ_RPB 16                    /* rows per block (4 warps x 4 rows) */
#define ADJ_BLOCKS (BBATCH*SSZ*SSZ/ADJ_RPB)   /* 36864 */

__global__ void stage1(const float* __restrict__ adj, const float* __restrict__ X,
                       const float* __restrict__ W0) {
    if (blockIdx.x < NQ_BLOCKS) {
        nt_core<0, DD, HH>(blockIdx.x, X, W0, nullptr, g_Q);
        return;
    }
    // adj reduction: A0 = sum_e adj, A1 = sum_e adj*we
    int bid = blockIdx.x - NQ_BLOCKS;
    int wid = threadIdx.x >> 5, lane = threadIdx.x & 31;
    long long r0 = (long long)bid * ADJ_RPB + wid * 4;
    float w0 = 0.f, w1 = 0.f;
    if (lane < 25) { w0 = g_we[2*lane]; w1 = g_we[2*lane + 1]; }
    float s0[4] = {}, s1[4] = {};
    if (lane < 25) {
        #pragma unroll
        for (int r = 0; r < 4; r++) {
            float2 v = ((const float2*)(adj + (r0 + r) * EE))[lane];
            s0[r] = v.x + v.y;
            s1[r] = fmaf(v.x, w0, v.y * w1);
        }
    }
    #pragma unroll
    for (int r = 0; r < 4; r++) {
        #pragma unroll
        for (int o = 16; o > 0; o >>= 1) {
            s0[r] += __shfl_down_sync(0xffffffffu, s0[r], o);
            s1[r] += __shfl_down_sync(0xffffffffu, s1[r], o);
        }
    }
    if (lane == 0) {
        #pragma unroll
        for (int r = 0; r < 4; r++) {
            g_A0[r0 + r] = s0[r];
            g_A1[r0 + r] = s1[r];
        }
    }
}

// ======================= batched NN GEMM (A[b] @ B[b]) ======================
// MODE 0: A=g_A0, B=g_Q, epilogue S0 = acc/E + Q + 2*b0
// MODE 1: A=g_A1, B=g_P, epilogue S1 = acc/E + (u' + (s2+sbh)T')/E + P + 2*b1
template<int MODE>
__global__ void gemm_bat(const float* __restrict__ bias) {
    int b = blockIdx.z;
    const float* A  = (MODE == 0 ? g_A0 : g_A1) + (size_t)b * SSZ * SSZ;
    const float* Bm = (MODE == 0 ? g_Q  : g_P ) + (size_t)b * SSZ * HH;
    __shared__ float As[16][68];
    __shared__ float Bs[16][36];
    int m0 = blockIdx.y * 64, n0 = blockIdx.x * 32;
    int tid = threadIdx.x;
    int lk = tid & 15, lm = tid >> 4;    // A loader
    int ln = tid & 31, lko = tid >> 5;   // B loader: k = lko*4+kc
    int tx = tid & 7,  ty = tid >> 3;
    const int NIT = SSZ / 16;            // 24

    float ar[8], br[4];
    float acc[4][4] = {};

    {
        #pragma unroll
        for (int mm = 0; mm < 8; mm++) ar[mm] = A[(m0 + lm*8 + mm) * SSZ + lk];
        int n = n0 + ln;
        #pragma unroll
        for (int kc = 0; kc < 4; kc++)
            br[kc] = (n < HH) ? Bm[(lko*4 + kc) * HH + n] : 0.f;
    }

    for (int it = 0; it < NIT; it++) {
        __syncthreads();
        #pragma unroll
        for (int mm = 0; mm < 8; mm++) As[lk][lm*8 + mm] = ar[mm];
        #pragma unroll
        for (int kc = 0; kc < 4; kc++) Bs[lko*4 + kc][ln] = br[kc];
        __syncthreads();

        if (it + 1 < NIT) {
            int k0 = (it + 1) * 16;
            #pragma unroll
            for (int mm = 0; mm < 8; mm++)
                ar[mm] = A[(m0 + lm*8 + mm) * SSZ + k0 + lk];
            int n = n0 + ln;
            #pragma unroll
            for (int kc = 0; kc < 4; kc++)
                br[kc] = (n < HH) ? Bm[(k0 + lko*4 + kc) * HH + n] : 0.f;
        }

        #pragma unroll
        for (int kk = 0; kk < 16; kk++) {
            float4 av = *(const float4*)&As[kk][ty*4];
            float4 bv = *(const float4*)&Bs[kk][tx*4];
            float a[4] = {av.x, av.y, av.z, av.w};
            float bb[4] = {bv.x, bv.y, bv.z, bv.w};
            #pragma unroll
            for (int i = 0; i < 4; i++)
                #pragma unroll
                for (int j = 0; j < 4; j++)
                    acc[i][j] = fmaf(a[i], bb[j], acc[i][j]);
        }
    }

    const float invE = 1.f / EE;
    #pragma unroll
    for (int i = 0; i < 4; i++) {
        int row = b * SSZ + m0 + ty*4 + i;
        #pragma unroll
        for (int j = 0; j < 4; j++) {
            int n = n0 + tx*4 + j;
            if (n < HH) {
                if (MODE == 0) {
                    g_S0[row*HH + n] = acc[i][j] * invE + g_Q[row*HH + n] + 2.f*bias[n];
                } else {
                    float corr = g_up[b*HH + n] + (g_s2[row] + g_sbh) * g_Tp[b*HH + n];
                    g_S1[row*HH + n] = (acc[i][j] + corr) * invE + g_P[row*HH + n] + 2.f*bias[n];
                }
            }
        }
    }
}

// ======================= P GEMM + s1/s2 rows ================================
__global__ void gemm_p(const float* __restrict__ X, const float* __restrict__ W1) {
    if (blockIdx.x < NQ_BLOCKS) {
        nt_core<1, D1, HH>(blockIdx.x, X, W1, nullptr, g_P);
        return;
    }
    // s1/s2: one thread per row over g0 = relu(S0)
    int row = (blockIdx.x - NQ_BLOCKS) * 128 + threadIdx.x;
    if (row >= BSR) return;
    const float* s0 = g_S0 + row * HH;
    float a = 0.f, b = 0.f;
    for (int j = 0; j < HH; j++) {
        float g = fmaxf(s0[j], 0.f);
        a = fmaf(g, g_w1s[j], a);
        b = fmaf(g, g_w2s[j], b);
    }
    g_s1[row] = a;
    g_s2[row] = b;
}

// ======================= colsum of P: T', u' ================================
__global__ void colsum_p() {
    int b = blockIdx.x;
    int j = threadIdx.x;
    if (j >= HH) return;
    const float* Pp = g_P + (size_t)b * SSZ * HH;
    const float* s1 = g_s1 + b * SSZ;
    float T = 0.f, u = 0.f;
    for (int s = 0; s < SSZ; s++) {
        float v = Pp[s*HH + j];
        T += v;
        u = fmaf(s1[s], v, u);
    }
    g_Tp[b*HH + j] = T;
    g_up[b*HH + j] = u;
}

// ======================= final GEMM =========================================
__global__ void gemm_out(const float* __restrict__ X, const float* __restrict__ Wout,
                         const float* __restrict__ bout, float* __restrict__ out) {
    nt_core<2, DD, DD>(blockIdx.x, X, Wout, bout, out);
}

// ======================= launch =============================================
extern "C" void kernel_launch(void* const* d_in, const int* in_sizes, int n_in,
                              void* d_out, int out_size) {
    const float* adj  = (const float*)d_in[0];
    const float* X    = (const float*)d_in[1];
    const float* W0   = (const float*)d_in[2];
    const float* b0   = (const float*)d_in[3];
    const float* W1   = (const float*)d_in[4];
    const float* b1   = (const float*)d_in[5];
    const float* Wh   = (const float*)d_in[6];
    const float* bh   = (const float*)d_in[7];
    const float* Wout = (const float*)d_in[8];
    const float* bout = (const float*)d_in[9];
    float* out = (float*)d_out;

    prep_weights<<<1, 256>>>(Wh, bh);

    // Q = X@W0^T overlapped with the 118MB adj streaming pass
    stage1<<<NQ_BLOCKS + ADJ_BLOCKS, 128>>>(adj, X, W0);

    // S0 = A0@Q/E + Q + 2b0   (g0 = relu(S0) applied on read downstream)
    gemm_bat<0><<<dim3(5, 6, BBATCH), 128>>>(b0);

    // P = [X|g0]@W1^T   plus s1/s2 row reductions
    gemm_p<<<NQ_BLOCKS + (BSR + 127) / 128, 128>>>(X, W1);

    // T' = colsum(P), u' = s1-weighted colsum(P)
    colsum_p<<<BBATCH, 160>>>();

    // S1 = (A1@P + u' + (s2+sbh)T')/E + P + 2b1
    gemm_bat<1><<<dim3(5, 6, BBATCH), 128>>>(b1);

    // out = (X + relu([S0|S1])) @ Wout^T + bout
    gemm_out<<<240, 128>>>(X, Wout, bout, out);
}

// round 3
// speedup vs baseline: 1.3720x; 1.2615x over previous
#include <cuda_runtime.h>

#define BBATCH 4
#define SSZ 384
#define DD 300
#define EE 50
#define HH 150
#define BSR (BBATCH*SSZ)   /* 1536 */
#define D1 450
#define INVE (1.0f/50.0f)

// ---------------- device scratch ----------------
__device__ float g_we[EE];
__device__ float g_w1s[HH];
__device__ float g_w2s[HH];
__device__ float g_sbh;
__device__ float g_A0[BBATCH*SSZ*SSZ];
__device__ float g_A1[BBATCH*SSZ*SSZ];
__device__ float g_Q [BSR*HH];
__device__ float g_g0[BSR*HH];   // relu already applied
__device__ float g_P [BSR*HH];
__device__ float g_g1[BSR*HH];   // relu already applied
__device__ float g_OX[BSR*DD];
__device__ float g_s1[BSR];
__device__ float g_s2[BSR];
__device__ float g_Tp[BBATCH*HH];
__device__ float g_up[BBATCH*HH];

// ---------------- prep: column sums of Wh splits, sum(bh) ------------------
__global__ void prep_weights(const float* __restrict__ Wh, const float* __restrict__ bh) {
    int t = threadIdx.x;
    const int WHC = 2*HH + EE;
    if (t < EE) {
        float s = 0.f;
        for (int f = 0; f < EE; f++) s += Wh[f*WHC + t];
        g_we[t] = s;
    }
    if (t < HH) {
        float a = 0.f, b = 0.f;
        for (int f = 0; f < EE; f++) {
            a += Wh[f*WHC + EE + t];
            b += Wh[f*WHC + EE + HH + t];
        }
        g_w1s[t] = a;
        g_w2s[t] = b;
    }
    if (t == 0) {
        float s = 0.f;
        for (int e = 0; e < EE; e++) s += bh[e];
        g_sbh = s;
    }
}

// ======================= NT GEMM 32x32 tile, 128 thr, 2x4 micro =============
// C[m,n] = sum_k A[m*lda+k] * W[n*ldw+k]   (+bias[n]) (+Cadd[m*ldc+n])
__device__ __forceinline__ void nt32(
    float (*As)[34], float (*Ws)[36],
    const float* __restrict__ A, int lda, int K,
    const float* __restrict__ W, int ldw,
    const float* __restrict__ bias,
    const float* __restrict__ Cadd,
    float* __restrict__ C, int ldc, int N,
    int m0, int n0)
{
    int tid = threadIdx.x;
    int lrow = tid >> 2, l4 = (tid & 3) * 4;
    int tx = tid & 7, ty = tid >> 3;
    int NIT = (K + 15) >> 4;

    const float* Arow = A + (size_t)(m0 + lrow) * lda;
    int nW = n0 + lrow;
    bool nok = (nW < N);
    const float* Wrow = W + (size_t)(nok ? nW : 0) * ldw;

    float ar[4], br[4];
    float acc[2][4] = {};

    #pragma unroll
    for (int i = 0; i < 4; i++) {
        int k = l4 + i;
        ar[i] = (k < K) ? Arow[k] : 0.f;
        br[i] = (nok && k < K) ? Wrow[k] : 0.f;
    }

    for (int it = 0; it < NIT; it++) {
        __syncthreads();
        #pragma unroll
        for (int i = 0; i < 4; i++) {
            As[l4 + i][lrow] = ar[i];
            Ws[l4 + i][lrow] = br[i];
        }
        __syncthreads();
        if (it + 1 < NIT) {
            int k0 = (it + 1) * 16;
            #pragma unroll
            for (int i = 0; i < 4; i++) {
                int k = k0 + l4 + i;
                ar[i] = (k < K) ? Arow[k] : 0.f;
                br[i] = (nok && k < K) ? Wrow[k] : 0.f;
            }
        }
        #pragma unroll
        for (int kk = 0; kk < 16; kk++) {
            float2 a = *(const float2*)&As[kk][ty * 2];
            float4 b = *(const float4*)&Ws[kk][tx * 4];
            acc[0][0] = fmaf(a.x, b.x, acc[0][0]);
            acc[0][1] = fmaf(a.x, b.y, acc[0][1]);
            acc[0][2] = fmaf(a.x, b.z, acc[0][2]);
            acc[0][3] = fmaf(a.x, b.w, acc[0][3]);
            acc[1][0] = fmaf(a.y, b.x, acc[1][0]);
            acc[1][1] = fmaf(a.y, b.y, acc[1][1]);
            acc[1][2] = fmaf(a.y, b.z, acc[1][2]);
            acc[1][3] = fmaf(a.y, b.w, acc[1][3]);
        }
    }

    #pragma unroll
    for (int i = 0; i < 2; i++) {
        int m = m0 + ty * 2 + i;
        #pragma unroll
        for (int j = 0; j < 4; j++) {
            int n = n0 + tx * 4 + j;
            if (n < N) {
                float v = acc[i][j];
                if (bias) v += bias[n];
                if (Cadd) v += Cadd[(size_t)m * ldc + n];
                C[(size_t)m * ldc + n] = v;
            }
        }
    }
}

// ======================= stage1: Q, PX, OX GEMMs + adj reduction ============
#define QB 240                  /* 48 m-tiles x 5 n-tiles */
#define PXB 240
#define OXB 480                 /* 48 x 10 */
#define GEMMB (QB+PXB+OXB)      /* 960 */
#define ADJ_RPB 16
#define ADJ_BLOCKS (BBATCH*SSZ*SSZ/ADJ_RPB)   /* 36864 */

__global__ void stage1(const float* __restrict__ adj, const float* __restrict__ X,
                       const float* __restrict__ W0, const float* __restrict__ W1,
                       const float* __restrict__ Wout, const float* __restrict__ bout) {
    __shared__ float As[16][34];
    __shared__ float Ws[16][36];
    int bx = blockIdx.x;
    if (bx < QB) {  // Q = X @ W0^T
        nt32(As, Ws, X, DD, DD, W0, DD, nullptr, nullptr, g_Q, HH, HH,
             (bx / 5) * 32, (bx % 5) * 32);
        return;
    }
    bx -= QB;
    if (bx < PXB) { // PX = X @ W1[:, :300]^T   (into g_P)
        nt32(As, Ws, X, DD, DD, W1, D1, nullptr, nullptr, g_P, HH, HH,
             (bx / 5) * 32, (bx % 5) * 32);
        return;
    }
    bx -= PXB;
    if (bx < OXB) { // OX = X @ Wout^T + bout
        nt32(As, Ws, X, DD, DD, Wout, DD, bout, nullptr, g_OX, DD, DD,
             (bx / 10) * 32, (bx % 10) * 32);
        return;
    }
    bx -= OXB;
    // adj reduction: A0 = sum_e adj, A1 = sum_e adj*we. 16 rows/block.
    int wid = threadIdx.x >> 5, lane = threadIdx.x & 31;
    long long r0 = (long long)bx * ADJ_RPB + wid * 4;
    float w0 = 0.f, w1 = 0.f;
    if (lane < 25) { w0 = g_we[2*lane]; w1 = g_we[2*lane + 1]; }
    float s0[4] = {}, s1[4] = {};
    if (lane < 25) {
        #pragma unroll
        for (int r = 0; r < 4; r++) {
            float2 v = ((const float2*)(adj + (r0 + r) * EE))[lane];
            s0[r] = v.x + v.y;
            s1[r] = fmaf(v.x, w0, v.y * w1);
        }
    }
    #pragma unroll
    for (int r = 0; r < 4; r++) {
        #pragma unroll
        for (int o = 16; o > 0; o >>= 1) {
            s0[r] += __shfl_down_sync(0xffffffffu, s0[r], o);
            s1[r] += __shfl_down_sync(0xffffffffu, s1[r], o);
        }
    }
    if (lane == 0) {
        #pragma unroll
        for (int r = 0; r < 4; r++) {
            g_A0[r0 + r] = s0[r];
            g_A1[r0 + r] = s1[r];
        }
    }
}

// ======================= batched NN GEMM 32x32 (A[b] @ B[b]) ================
// MODE 0: g0 = relu(A0@Q/E + Q + 2*b0)
// MODE 1: g1 = relu((A1@P + u' + (s2+sbh)T')/E + P + 2*b1)
template<int MODE>
__global__ void gemm_bat(const float* __restrict__ bias) {
    __shared__ float As[16][34];
    __shared__ float Bs[16][36];
    int b = blockIdx.z;
    const float* A  = (MODE == 0 ? g_A0 : g_A1) + (size_t)b * SSZ * SSZ;
    const float* Bm = (MODE == 0 ? g_Q  : g_P ) + (size_t)b * SSZ * HH;
    int m0 = blockIdx.y * 32, n0 = blockIdx.x * 32;
    int tid = threadIdx.x;
    int lrow = tid >> 2, l4 = (tid & 3) * 4;     // A loader
    int lkb = tid >> 3, ln4 = (tid & 7) * 4;     // B loader
    int tx = tid & 7, ty = tid >> 3;
    const int NIT = SSZ / 16;                    // 24

    const float* Arow = A + (size_t)(m0 + lrow) * SSZ;
    float ar[4], br[4];
    float acc[2][4] = {};

    #pragma unroll
    for (int i = 0; i < 4; i++) ar[i] = Arow[l4 + i];
    #pragma unroll
    for (int i = 0; i < 4; i++) {
        int n = n0 + ln4 + i;
        br[i] = (n < HH) ? Bm[lkb * HH + n] : 0.f;
    }

    for (int it = 0; it < NIT; it++) {
        __syncthreads();
        #pragma unroll
        for (int i = 0; i < 4; i++) As[l4 + i][lrow] = ar[i];
        #pragma unroll
        for (int i = 0; i < 4; i++) Bs[lkb][ln4 + i] = br[i];
        __syncthreads();
        if (it + 1 < NIT) {
            int k0 = (it + 1) * 16;
            #pragma unroll
            for (int i = 0; i < 4; i++) ar[i] = Arow[k0 + l4 + i];
            #pragma unroll
            for (int i = 0; i < 4; i++) {
                int n = n0 + ln4 + i;
                br[i] = (n < HH) ? Bm[(k0 + lkb) * HH + n] : 0.f;
            }
        }
        #pragma unroll
        for (int kk = 0; kk < 16; kk++) {
            float2 a = *(const float2*)&As[kk][ty * 2];
            float4 bb = *(const float4*)&Bs[kk][tx * 4];
            acc[0][0] = fmaf(a.x, bb.x, acc[0][0]);
            acc[0][1] = fmaf(a.x, bb.y, acc[0][1]);
            acc[0][2] = fmaf(a.x, bb.z, acc[0][2]);
            acc[0][3] = fmaf(a.x, bb.w, acc[0][3]);
            acc[1][0] = fmaf(a.y, bb.x, acc[1][0]);
            acc[1][1] = fmaf(a.y, bb.y, acc[1][1]);
            acc[1][2] = fmaf(a.y, bb.z, acc[1][2]);
            acc[1][3] = fmaf(a.y, bb.w, acc[1][3]);
        }
    }

    #pragma unroll
    for (int i = 0; i < 2; i++) {
        int row = b * SSZ + m0 + ty * 2 + i;
        #pragma unroll
        for (int j = 0; j < 4; j++) {
            int n = n0 + tx * 4 + j;
            if (n < HH) {
                float v;
                if (MODE == 0) {
                    v = acc[i][j] * INVE + g_Q[row*HH + n] + 2.f * bias[n];
                    g_g0[row*HH + n] = fmaxf(v, 0.f);
                } else {
                    float corr = g_up[b*HH + n] + (g_s2[row] + g_sbh) * g_Tp[b*HH + n];
                    v = (acc[i][j] + corr) * INVE + g_P[row*HH + n] + 2.f * bias[n];
                    g_g1[row*HH + n] = fmaxf(v, 0.f);
                }
            }
        }
    }
}

// ======================= stage3: P += g0@W1b^T, OX += g0@WoutA^T, s1/s2 =====
#define PAB 240
#define OAB 480
__global__ void stage3(const float* __restrict__ W1, const float* __restrict__ Wout) {
    __shared__ float As[16][34];
    __shared__ float Ws[16][36];
    int bx = blockIdx.x;
    if (bx < PAB) {  // P += g0 @ W1[:, 300:]^T
        nt32(As, Ws, g_g0, HH, HH, W1 + DD, D1, nullptr, g_P, g_P, HH, HH,
             (bx / 5) * 32, (bx % 5) * 32);
        return;
    }
    bx -= PAB;
    if (bx < OAB) {  // OX += g0 @ Wout[:, :150]^T
        nt32(As, Ws, g_g0, HH, HH, Wout, DD, nullptr, g_OX, g_OX, DD, DD,
             (bx / 10) * 32, (bx % 10) * 32);
        return;
    }
    bx -= OAB;
    // s1/s2: one thread per row of g0
    int row = bx * 128 + threadIdx.x;   // 12 blocks x 128 = 1536
    const float* g = g_g0 + (size_t)row * HH;
    float a = 0.f, b2 = 0.f;
    for (int j = 0; j < HH; j++) {
        float v = g[j];
        a  = fmaf(v, g_w1s[j], a);
        b2 = fmaf(v, g_w2s[j], b2);
    }
    g_s1[row] = a;
    g_s2[row] = b2;
}

// ======================= colsum of P: T', u' ================================
__global__ void colsum_p() {
    int b = blockIdx.x / 5, jc = blockIdx.x % 5;
    int t = threadIdx.x;
    int jl = t >> 2, part = t & 3;       // 32 j-lanes (30 used) x 4 parts
    int j = jc * 30 + jl;
    __shared__ float sT[32][4], sU[32][4];
    float T = 0.f, u = 0.f;
    if (jl < 30) {
        const float* P  = g_P + (size_t)b * SSZ * HH;
        const float* s1 = g_s1 + b * SSZ;
        int s_end = part * 96 + 96;
        for (int s = part * 96; s < s_end; s++) {
            float v = P[s * HH + j];
            T += v;
            u = fmaf(s1[s], v, u);
        }
    }
    sT[jl][part] = T;
    sU[jl][part] = u;
    __syncthreads();
    if (part == 0 && jl < 30) {
        g_Tp[b*HH + j] = sT[jl][0] + sT[jl][1] + sT[jl][2] + sT[jl][3];
        g_up[b*HH + j] = sU[jl][0] + sU[jl][1] + sU[jl][2] + sU[jl][3];
    }
}

// ======================= stage6: out = OX + g1@WoutB^T ======================
__global__ void stage6(const float* __restrict__ Wout, float* __restrict__ out) {
    __shared__ float As[16][34];
    __shared__ float Ws[16][36];
    int bx = blockIdx.x;
    nt32(As, Ws, g_g1, HH, HH, Wout + HH, DD, nullptr, g_OX, out, DD, DD,
         (bx / 10) * 32, (bx % 10) * 32);
}

// ======================= launch =============================================
extern "C" void kernel_launch(void* const* d_in, const int* in_sizes, int n_in,
                              void* d_out, int out_size) {
    const float* adj  = (const float*)d_in[0];
    const float* X    = (const float*)d_in[1];
    const float* W0   = (const float*)d_in[2];
    const float* b0   = (const float*)d_in[3];
    const float* W1   = (const float*)d_in[4];
    const float* b1   = (const float*)d_in[5];
    const float* Wh   = (const float*)d_in[6];
    const float* bh   = (const float*)d_in[7];
    const float* Wout = (const float*)d_in[8];
    const float* bout = (const float*)d_in[9];
    float* out = (float*)d_out;

    prep_weights<<<1, 256>>>(Wh, bh);

    // Q, PX, OX GEMMs overlapped with 118MB adj streaming pass
    stage1<<<GEMMB + ADJ_BLOCKS, 128>>>(adj, X, W0, W1, Wout, bout);

    // g0 = relu(A0@Q/E + Q + 2b0)
    gemm_bat<0><<<dim3(5, 12, BBATCH), 128>>>(b0);

    // P += g0@W1b^T ; OX += g0@WoutA^T ; s1/s2
    stage3<<<PAB + OAB + 12, 128>>>(W1, Wout);

    // T' = colsum(P), u' = s1-weighted colsum(P)
    colsum_p<<<BBATCH * 5, 128>>>();

    // g1 = relu((A1@P + u' + (s2+sbh)T')/E + P + 2b1)
    gemm_bat<1><<<dim3(5, 12, BBATCH), 128>>>(b1);

    // out = OX + g1@WoutB^T
    stage6<<<OAB, 128>>>(Wout, out);
}

// round 4
// speedup vs baseline: 1.4942x; 1.0891x over previous
#include <cuda_runtime.h>

#define BBATCH 4
#define SSZ 384
#define DD 300
#define EE 50
#define HH 150
#define BSR (BBATCH*SSZ)   /* 1536 */
#define D1 450
#define INVE (1.0f/50.0f)

// ---------------- device scratch ----------------
__device__ float g_we[EE];
__device__ float g_w1s[HH];
__device__ float g_w2s[HH];
__device__ float g_sbh;
__device__ float g_A0[BBATCH*SSZ*SSZ];
__device__ float g_A1[BBATCH*SSZ*SSZ];
__device__ float g_Q [BSR*HH];
__device__ float g_g0[BSR*HH];   // relu applied
__device__ float g_P [BSR*HH];
__device__ float g_g1[BSR*HH];   // relu applied
__device__ float g_OX[BSR*DD];
__device__ float g_s1[BSR];
__device__ float g_s2[BSR];

// ---------------- prep: Wh column sums, sum(bh), zero s1/s2 ----------------
__global__ void prep_weights(const float* __restrict__ Wh, const float* __restrict__ bh) {
    int t = threadIdx.x;
    const int WHC = 2*HH + EE;
    if (t < EE) {
        float s = 0.f;
        for (int f = 0; f < EE; f++) s += Wh[f*WHC + t];
        g_we[t] = s;
    }
    if (t < HH) {
        float a = 0.f, b = 0.f;
        for (int f = 0; f < EE; f++) {
            a += Wh[f*WHC + EE + t];
            b += Wh[f*WHC + EE + HH + t];
        }
        g_w1s[t] = a;
        g_w2s[t] = b;
    }
    if (t == 0) {
        float s = 0.f;
        for (int e = 0; e < EE; e++) s += bh[e];
        g_sbh = s;
    }
    for (int i = t; i < BSR; i += 256) { g_s1[i] = 0.f; g_s2[i] = 0.f; }
}

// =================== Core A: NT GEMM 64x64 tile, 128 thr, 8x4 micro ========
// C[m,n] = sum_k A[m*lda+k]*W[n*ldw+k] (+bias) (+Cadd). M divisible by 64.
__device__ __forceinline__ void ldpair(float* dst, const float* __restrict__ p,
                                       int k0, int K, bool ok) {
    #pragma unroll
    for (int j = 0; j < 4; j++) {
        int k = k0 + 2*j;
        float2 v = (ok && k < K) ? *(const float2*)(p + k) : make_float2(0.f, 0.f);
        dst[2*j] = v.x; dst[2*j+1] = v.y;
    }
}

__device__ __forceinline__ void ntA(
    float (*As)[68], float (*Ws)[68],
    const float* __restrict__ A, int lda, int K,
    const float* __restrict__ W, int ldw, int N,
    int m0, int n0,
    const float* __restrict__ bias, const float* __restrict__ Cadd,
    float* __restrict__ C, int ldc)
{
    int tid = threadIdx.x;
    int lrow = tid >> 1, l8 = (tid & 1) * 8;
    int tx = tid & 15, ty = tid >> 4;
    int NIT = (K + 15) >> 4;

    const float* Arow = A + (size_t)(m0 + lrow) * lda;
    int nW = n0 + lrow;
    bool nok = (nW < N);
    const float* Wrow = W + (size_t)(nok ? nW : 0) * ldw;

    float ar[8], br[8];
    float acc[8][4] = {};

    ldpair(ar, Arow, l8, K, true);
    ldpair(br, Wrow, l8, K, nok);

    for (int it = 0; it < NIT; it++) {
        __syncthreads();
        #pragma unroll
        for (int j = 0; j < 8; j++) {
            As[l8 + j][lrow] = ar[j];
            Ws[l8 + j][lrow] = br[j];
        }
        __syncthreads();
        if (it + 1 < NIT) {
            int k0 = (it + 1) * 16;
            ldpair(ar, Arow, k0 + l8, K, true);
            ldpair(br, Wrow, k0 + l8, K, nok);
        }
        #pragma unroll
        for (int kk = 0; kk < 16; kk++) {
            float4 a0 = *(const float4*)&As[kk][ty*8];
            float4 a1 = *(const float4*)&As[kk][ty*8 + 4];
            float4 b  = *(const float4*)&Ws[kk][tx*4];
            float am[8] = {a0.x,a0.y,a0.z,a0.w,a1.x,a1.y,a1.z,a1.w};
            float bn[4] = {b.x,b.y,b.z,b.w};
            #pragma unroll
            for (int i = 0; i < 8; i++)
                #pragma unroll
                for (int j = 0; j < 4; j++)
                    acc[i][j] = fmaf(am[i], bn[j], acc[i][j]);
        }
    }

    #pragma unroll
    for (int i = 0; i < 8; i++) {
        int m = m0 + ty*8 + i;
        #pragma unroll
        for (int j = 0; j < 4; j++) {
            int n = n0 + tx*4 + j;
            if (n < N) {
                float v = acc[i][j];
                if (bias) v += bias[n];
                if (Cadd) v += Cadd[(size_t)m*ldc + n];
                C[(size_t)m*ldc + n] = v;
            }
        }
    }
}

// =================== stage1: Q, PX, OX GEMMs + adj reduction ================
#define QB 72                   /* 24 m x 3 n */
#define PXB 72
#define OXB 120                 /* 24 m x 5 n */
#define GEMMB (QB+PXB+OXB)      /* 264 */
#define ADJ_RPB 64
#define ADJ_BLOCKS (BBATCH*SSZ*SSZ/ADJ_RPB)   /* 9216 */

__global__ __launch_bounds__(128) void stage1(
    const float* __restrict__ adj, const float* __restrict__ X,
    const float* __restrict__ W0, const float* __restrict__ W1,
    const float* __restrict__ Wout, const float* __restrict__ bout)
{
    int bx = blockIdx.x;
    if (bx < GEMMB) {
        __shared__ __align__(16) float As[16][68];
        __shared__ __align__(16) float Ws[16][68];
        if (bx < QB) {          // Q = X @ W0^T
            ntA(As, Ws, X, DD, DD, W0, DD, HH, (bx/3)*64, (bx%3)*64,
                nullptr, nullptr, g_Q, HH);
        } else if (bx < QB + PXB) {  // PX = X @ W1[:, :300]^T
            int t = bx - QB;
            ntA(As, Ws, X, DD, DD, W1, D1, HH, (t/3)*64, (t%3)*64,
                nullptr, nullptr, g_P, HH);
        } else {                // OX = X @ Wout^T + bout
            int t = bx - QB - PXB;
            ntA(As, Ws, X, DD, DD, Wout, DD, DD, (t/5)*64, (t%5)*64,
                bout, nullptr, g_OX, DD);
        }
        return;
    }
    // ---- adj reduction: 64 rows/block, smem-staged ----
    __shared__ float buf[ADJ_RPB][51];
    __shared__ float swe[EE];
    int tid = threadIdx.x;
    if (tid < EE) swe[tid] = g_we[tid];
    size_t r0 = (size_t)(bx - GEMMB) * ADJ_RPB;
    const float4* src = (const float4*)(adj + r0 * EE);
    for (int idx = tid; idx < ADJ_RPB*EE/4; idx += 128) {
        float4 v = src[idx];
        int g = idx * 4;
        buf[(g  )/EE][(g  )%EE] = v.x;
        buf[(g+1)/EE][(g+1)%EE] = v.y;
        buf[(g+2)/EE][(g+2)%EE] = v.z;
        buf[(g+3)/EE][(g+3)%EE] = v.w;
    }
    __syncthreads();
    if (tid < ADJ_RPB) {
        float s0 = 0.f, s1 = 0.f;
        #pragma unroll 10
        for (int e = 0; e < EE; e++) {
            float v = buf[tid][e];
            s0 += v;
            s1 = fmaf(v, swe[e], s1);
        }
        g_A0[r0 + tid] = s0;
        g_A1[r0 + tid] = s1;
    }
}

// ============= Core B: batched NN GEMM 32x64, 128 thr, 4x4 micro ============
// MODE 0: g0 = relu(A0@Q/E + Q + 2*b0) ; atomics for s1/s2
// MODE 1: g1 = relu(Atilde1@P/E + P + 2*b1), Atilde1 = A1 + s1[k] + s2[i] + sbh
template<int MODE>
__global__ __launch_bounds__(128) void gemm_bat(const float* __restrict__ bias) {
    __shared__ __align__(16) float As[16][36];
    __shared__ __align__(16) float Bs[16][68];
    int b = blockIdx.z;
    const float* A  = (MODE == 0 ? g_A0 : g_A1) + (size_t)b * SSZ * SSZ;
    const float* Bm = (MODE == 0 ? g_Q  : g_P ) + (size_t)b * SSZ * HH;
    int m0 = blockIdx.y * 32, n0 = blockIdx.x * 64;
    int tid = threadIdx.x;
    int arow = tid >> 2, l4 = (tid & 3) * 4;    // A loader: 1 float4 per iter
    int lkb = tid >> 3, n8 = (tid & 7) * 8;     // B loader: 4 float2 per iter
    int tx = tid & 15, ty = tid >> 4;
    const int NIT = SSZ / 16;                   // 24

    const float* Arow = A + (size_t)(m0 + arow) * SSZ;
    const float* s1p = g_s1 + b * SSZ;
    float s2i = 0.f;
    if (MODE == 1) s2i = g_s2[b*SSZ + m0 + arow] + g_sbh;

    float ar[4], br[8];
    float acc[4][4] = {};

    {
        float4 av = *(const float4*)(Arow + l4);
        if (MODE == 1) {
            float4 sv = *(const float4*)(s1p + l4);
            av.x += sv.x + s2i; av.y += sv.y + s2i;
            av.z += sv.z + s2i; av.w += sv.w + s2i;
        }
        ar[0]=av.x; ar[1]=av.y; ar[2]=av.z; ar[3]=av.w;
        #pragma unroll
        for (int t = 0; t < 4; t++) {
            int n = n0 + n8 + 2*t;
            float2 v = (n < HH) ? *(const float2*)(Bm + (size_t)lkb*HH + n)
                                : make_float2(0.f, 0.f);
            br[2*t] = v.x; br[2*t+1] = v.y;
        }
    }

    for (int it = 0; it < NIT; it++) {
        __syncthreads();
        #pragma unroll
        for (int j = 0; j < 4; j++) As[l4 + j][arow] = ar[j];
        #pragma unroll
        for (int j = 0; j < 8; j++) Bs[lkb][n8 + j] = br[j];
        __syncthreads();
        if (it + 1 < NIT) {
            int k0 = (it + 1) * 16;
            float4 av = *(const float4*)(Arow + k0 + l4);
            if (MODE == 1) {
                float4 sv = *(const float4*)(s1p + k0 + l4);
                av.x += sv.x + s2i; av.y += sv.y + s2i;
                av.z += sv.z + s2i; av.w += sv.w + s2i;
            }
            ar[0]=av.x; ar[1]=av.y; ar[2]=av.z; ar[3]=av.w;
            #pragma unroll
            for (int t = 0; t < 4; t++) {
                int n = n0 + n8 + 2*t;
                float2 v = (n < HH) ? *(const float2*)(Bm + (size_t)(k0+lkb)*HH + n)
                                    : make_float2(0.f, 0.f);
                br[2*t] = v.x; br[2*t+1] = v.y;
            }
        }
        #pragma unroll
        for (int kk = 0; kk < 16; kk++) {
            float4 a = *(const float4*)&As[kk][ty*4];
            float4 bb = *(const float4*)&Bs[kk][tx*4];
            float am[4] = {a.x,a.y,a.z,a.w};
            float bn[4] = {bb.x,bb.y,bb.z,bb.w};
            #pragma unroll
            for (int i = 0; i < 4; i++)
                #pragma unroll
                for (int j = 0; j < 4; j++)
                    acc[i][j] = fmaf(am[i], bn[j], acc[i][j]);
        }
    }

    #pragma unroll
    for (int i = 0; i < 4; i++) {
        int row = b*SSZ + m0 + ty*4 + i;
        float p1 = 0.f, p2 = 0.f;
        #pragma unroll
        for (int j = 0; j < 4; j++) {
            int n = n0 + tx*4 + j;
            if (n < HH) {
                if (MODE == 0) {
                    float v = acc[i][j]*INVE + g_Q[(size_t)row*HH + n] + 2.f*bias[n];
                    float g = fmaxf(v, 0.f);
                    g_g0[(size_t)row*HH + n] = g;
                    p1 = fmaf(g, g_w1s[n], p1);
                    p2 = fmaf(g, g_w2s[n], p2);
                } else {
                    float v = acc[i][j]*INVE + g_P[(size_t)row*HH + n] + 2.f*bias[n];
                    g_g1[(size_t)row*HH + n] = fmaxf(v, 0.f);
                }
            }
        }
        if (MODE == 0) {
            atomicAdd(&g_s1[row], p1);
            atomicAdd(&g_s2[row], p2);
        }
    }
}

// =================== stage3: P += g0@W1b^T ; OX += g0@WoutA^T ===============
#define PAB 72     /* 24 x 3 */
#define OAB 120    /* 24 x 5 */
__global__ __launch_bounds__(128) void stage3(const float* __restrict__ W1,
                                              const float* __restrict__ Wout) {
    __shared__ __align__(16) float As[16][68];
    __shared__ __align__(16) float Ws[16][68];
    int bx = blockIdx.x;
    if (bx < PAB) {
        ntA(As, Ws, g_g0, HH, HH, W1 + DD, D1, HH, (bx/3)*64, (bx%3)*64,
            nullptr, g_P, g_P, HH);
    } else {
        int t = bx - PAB;
        ntA(As, Ws, g_g0, HH, HH, Wout, DD, DD, (t/5)*64, (t%5)*64,
            nullptr, g_OX, g_OX, DD);
    }
}

// =================== stage6: out = OX + g1@WoutB^T ==========================
__global__ __launch_bounds__(128) void stage6(const float* __restrict__ Wout,
                                              float* __restrict__ out) {
    __shared__ __align__(16) float As[16][68];
    __shared__ __align__(16) float Ws[16][68];
    int bx = blockIdx.x;
    ntA(As, Ws, g_g1, HH, HH, Wout + HH, DD, DD, (bx/5)*64, (bx%5)*64,
        nullptr, g_OX, out, DD);
}

// =================== launch =================================================
extern "C" void kernel_launch(void* const* d_in, const int* in_sizes, int n_in,
                              void* d_out, int out_size) {
    const float* adj  = (const float*)d_in[0];
    const float* X    = (const float*)d_in[1];
    const float* W0   = (const float*)d_in[2];
    const float* b0   = (const float*)d_in[3];
    const float* W1   = (const float*)d_in[4];
    const float* b1   = (const float*)d_in[5];
    const float* Wh   = (const float*)d_in[6];
    const float* bh   = (const float*)d_in[7];
    const float* Wout = (const float*)d_in[8];
    const float* bout = (const float*)d_in[9];
    float* out = (float*)d_out;

    prep_weights<<<1, 256>>>(Wh, bh);

    // Q, PX, OX GEMMs overlapped with the 118MB adj streaming pass
    stage1<<<GEMMB + ADJ_BLOCKS, 128>>>(adj, X, W0, W1, Wout, bout);

    // g0 = relu(A0@Q/E + Q + 2b0) ; s1/s2 via atomics
    gemm_bat<0><<<dim3(3, 12, BBATCH), 128>>>(b0);

    // P += g0@W1b^T ; OX += g0@WoutA^T
    stage3<<<PAB + OAB, 128>>>(W1, Wout);

    // g1 = relu(Atilde1@P/E + P + 2b1)   (rank-2 correction folded into A)
    gemm_bat<1><<<dim3(3, 12, BBATCH), 128>>>(b1);

    // out = OX + g1@WoutB^T
    stage6<<<OAB, 128>>>(Wout, out);
}

// round 5
// speedup vs baseline: 1.8400x; 1.2315x over previous
#include <cuda_runtime.h>

#define BBATCH 4
#define SSZ 384
#define DD 300
#define EE 50
#define HH 150
#define BSR (BBATCH*SSZ)   /* 1536 */
#define D1 450
#define INVE (1.0f/50.0f)

// ---------------- device scratch ----------------
__device__ float g_we[EE];
__device__ float g_w1s[HH];
__device__ float g_w2s[HH];
__device__ float g_sbh;
__device__ float g_A0[BBATCH*SSZ*SSZ];
__device__ float g_A1[BBATCH*SSZ*SSZ];
__device__ float g_Q [BSR*HH];
__device__ float g_P [BSR*HH];
__device__ float g_OX[BSR*DD];
__device__ float g_s1[BSR];
__device__ float g_s2[BSR];
__device__ float g_c0a[BSR*HH];   // bat0 split-K partials
__device__ float g_c0b[BSR*HH];
__device__ float g_c1a[BSR*HH];   // bat1 split-K partials
__device__ float g_c1b[BSR*HH];

// ---------------- prep ------------------------------------------------------
__global__ void prep_weights(const float* __restrict__ Wh, const float* __restrict__ bh) {
    int t = threadIdx.x;
    const int WHC = 2*HH + EE;
    if (t < EE) {
        float s = 0.f;
        for (int f = 0; f < EE; f++) s += Wh[f*WHC + t];
        g_we[t] = s;
    }
    if (t < HH) {
        float a = 0.f, b = 0.f;
        for (int f = 0; f < EE; f++) {
            a += Wh[f*WHC + EE + t];
            b += Wh[f*WHC + EE + HH + t];
        }
        g_w1s[t] = a;
        g_w2s[t] = b;
    }
    if (t == 0) {
        float s = 0.f;
        for (int e = 0; e < EE; e++) s += bh[e];
        g_sbh = s;
    }
}

// ---- A-operand loader: raw fp32 (ASRC 0), g0-epilogue (1), g1-epilogue (2) --
// loads k = kq..kq+3 and kq+8..kq+11 into ar[0..7]
template<int ASRC>
__device__ __forceinline__ void ldA8(float* ar, const float* __restrict__ A, int lda,
                                     const float* __restrict__ ba,
                                     int m, int kq, int K) {
    if (ASRC == 0) {
        const float* p = A + (size_t)m * lda;
        #pragma unroll
        for (int h = 0; h < 2; h++) {
            int k = kq + h*8;
            float4 v = (k < K) ? *(const float4*)(p + k) : make_float4(0.f,0.f,0.f,0.f);
            ar[h*4+0]=v.x; ar[h*4+1]=v.y; ar[h*4+2]=v.z; ar[h*4+3]=v.w;
        }
    } else {
        const float* pa = (ASRC==1) ? g_c0a : g_c1a;
        const float* pb = (ASRC==1) ? g_c0b : g_c1b;
        const float* pq = (ASRC==1) ? g_Q   : g_P;
        size_t base = (size_t)m * HH;
        #pragma unroll
        for (int h = 0; h < 2; h++) {
            #pragma unroll
            for (int t = 0; t < 2; t++) {
                int k = kq + h*8 + t*2;
                float rx = 0.f, ry = 0.f;
                if (k < K) {
                    float2 a = *(const float2*)(pa + base + k);
                    float2 b = *(const float2*)(pb + base + k);
                    float2 q = *(const float2*)(pq + base + k);
                    float2 bb = *(const float2*)(ba + k);
                    rx = fmaxf(fmaf(a.x + b.x, INVE, q.x + 2.f*bb.x), 0.f);
                    ry = fmaxf(fmaf(a.y + b.y, INVE, q.y + 2.f*bb.y), 0.f);
                }
                ar[h*4 + t*2] = rx; ar[h*4 + t*2 + 1] = ry;
            }
        }
    }
}

// ======= NT GEMM core: 64x32 tile, 128 thr, 4x4 micro, C = A@W^T ============
template<int ASRC>
__device__ __forceinline__ void ntB(
    const float* __restrict__ A, int lda, int K,
    const float* __restrict__ baA,
    const float* __restrict__ W, int ldw, int N,
    int m0, int n0,
    const float* __restrict__ biasC, const float* __restrict__ Cadd,
    float* __restrict__ C, int ldc)
{
    __shared__ __align__(16) float As[16][68];
    __shared__ __align__(16) float Ws[16][36];
    int tid = threadIdx.x;
    int arow = tid >> 1, aq = (tid & 1) * 4;
    int wrow = tid >> 2, wq = (tid & 3) * 2;
    int tx = tid & 7, ty = tid >> 3;
    int NIT = (K + 15) >> 4;

    int mA = m0 + arow;
    int nW = n0 + wrow;
    bool nok = nW < N;
    const float* Wrow = W + (size_t)(nok ? nW : 0) * ldw;

    float ar[8], wr[4];
    float acc[4][4] = {};

    ldA8<ASRC>(ar, A, lda, baA, mA, aq, K);
    #pragma unroll
    for (int h = 0; h < 2; h++) {
        int k = wq + h*8;
        float2 v = (nok && k < K) ? *(const float2*)(Wrow + k) : make_float2(0.f,0.f);
        wr[h*2] = v.x; wr[h*2+1] = v.y;
    }

    for (int it = 0; it < NIT; it++) {
        __syncthreads();
        #pragma unroll
        for (int h = 0; h < 2; h++)
            #pragma unroll
            for (int j = 0; j < 4; j++)
                As[aq + h*8 + j][arow] = ar[h*4 + j];
        #pragma unroll
        for (int h = 0; h < 2; h++)
            #pragma unroll
            for (int j = 0; j < 2; j++)
                Ws[wq + h*8 + j][wrow] = wr[h*2 + j];
        __syncthreads();
        if (it + 1 < NIT) {
            int k0 = (it + 1) * 16;
            ldA8<ASRC>(ar, A, lda, baA, mA, k0 + aq, K);
            #pragma unroll
            for (int h = 0; h < 2; h++) {
                int k = k0 + wq + h*8;
                float2 v = (nok && k < K) ? *(const float2*)(Wrow + k) : make_float2(0.f,0.f);
                wr[h*2] = v.x; wr[h*2+1] = v.y;
            }
        }
        #pragma unroll
        for (int kk = 0; kk < 16; kk++) {
            float4 a = *(const float4*)&As[kk][ty*4];
            float4 w = *(const float4*)&Ws[kk][tx*4];
            float am[4] = {a.x,a.y,a.z,a.w};
            float wn[4] = {w.x,w.y,w.z,w.w};
            #pragma unroll
            for (int i = 0; i < 4; i++)
                #pragma unroll
                for (int j = 0; j < 4; j++)
                    acc[i][j] = fmaf(am[i], wn[j], acc[i][j]);
        }
    }

    #pragma unroll
    for (int i = 0; i < 4; i++) {
        int m = m0 + ty*4 + i;
        #pragma unroll
        for (int j = 0; j < 4; j++) {
            int n = n0 + tx*4 + j;
            if (n < N) {
                float v = acc[i][j];
                if (biasC) v += biasC[n];
                if (Cadd) v += Cadd[(size_t)m*ldc + n];
                C[(size_t)m*ldc + n] = v;
            }
        }
    }
}

// ======= stage1: Q, PX, OX GEMMs + adj reduction ============================
#define QB 120
#define PXB 120
#define OXB 240
#define GEMMB (QB+PXB+OXB)      /* 480 */
#define ADJ_RPB 64
#define ADJ_BLOCKS (BBATCH*SSZ*SSZ/ADJ_RPB)   /* 9216 */

__global__ __launch_bounds__(128) void stage1(
    const float* __restrict__ adj, const float* __restrict__ X,
    const float* __restrict__ W0, const float* __restrict__ W1,
    const float* __restrict__ Wout, const float* __restrict__ bout)
{
    int bx = blockIdx.x;
    if (bx < QB) {               // Q = X @ W0^T
        ntB<0>(X, DD, DD, nullptr, W0, DD, HH, (bx/5)*64, (bx%5)*32,
               nullptr, nullptr, g_Q, HH);
        return;
    }
    if (bx < QB + PXB) {         // PX = X @ W1[:, :300]^T
        int t = bx - QB;
        ntB<0>(X, DD, DD, nullptr, W1, D1, HH, (t/5)*64, (t%5)*32,
               nullptr, nullptr, g_P, HH);
        return;
    }
    if (bx < GEMMB) {            // OX = X @ Wout^T + bout
        int t = bx - QB - PXB;
        ntB<0>(X, DD, DD, nullptr, Wout, DD, DD, (t/10)*64, (t%10)*32,
               bout, nullptr, g_OX, DD);
        return;
    }
    // ---- adj reduction: 64 rows/block, smem-staged ----
    __shared__ float buf[ADJ_RPB][51];
    __shared__ float swe[EE];
    int tid = threadIdx.x;
    if (tid < EE) swe[tid] = g_we[tid];
    size_t r0 = (size_t)(bx - GEMMB) * ADJ_RPB;
    const float4* src = (const float4*)(adj + r0 * EE);
    for (int idx = tid; idx < ADJ_RPB*EE/4; idx += 128) {
        float4 v = src[idx];
        int g = idx * 4;
        buf[(g  )/EE][(g  )%EE] = v.x;
        buf[(g+1)/EE][(g+1)%EE] = v.y;
        buf[(g+2)/EE][(g+2)%EE] = v.z;
        buf[(g+3)/EE][(g+3)%EE] = v.w;
    }
    __syncthreads();
    if (tid < ADJ_RPB) {
        float s0 = 0.f, s1 = 0.f;
        #pragma unroll 10
        for (int e = 0; e < EE; e++) {
            float v = buf[tid][e];
            s0 += v;
            s1 = fmaf(v, swe[e], s1);
        }
        g_A0[r0 + tid] = s0;
        g_A1[r0 + tid] = s1;
    }
}

// ======= bat: batched NN GEMM, split-K x2, 64x32 tile, 128 thr ==============
// MODE 0: partial of A0@Q ; MODE 1: partial of Atilde1@P
template<int MODE>
__global__ __launch_bounds__(128) void bat() {
    __shared__ __align__(16) float As[16][68];
    __shared__ __align__(8)  float Bs[16][34];
    int zc = blockIdx.z;
    int b = zc >> 1, half = zc & 1;
    const float* A  = (MODE==0 ? g_A0 : g_A1) + (size_t)b * SSZ * SSZ;
    const float* Bm = (MODE==0 ? g_Q  : g_P ) + (size_t)b * SSZ * HH;
    float* Cp = (MODE==0) ? (half ? g_c0b : g_c0a) : (half ? g_c1b : g_c1a);
    int m0 = blockIdx.y * 64, n0 = blockIdx.x * 32;
    int tid = threadIdx.x;
    int arow = tid >> 1, aq = (tid & 1) * 4;
    int bk = tid >> 3, bn = (tid & 7) * 4;
    int tx = tid & 7, ty = tid >> 3;
    int kbase = half * 192;

    const float* Arow = A + (size_t)(m0 + arow) * SSZ + kbase;
    const float* s1p = g_s1 + b * SSZ + kbase;
    float s2i = 0.f;
    if (MODE == 1) s2i = g_s2[b*SSZ + m0 + arow] + g_sbh;

    float ar[8], br[4];
    float acc[4][4] = {};

    // prefetch it=0
    #pragma unroll
    for (int h = 0; h < 2; h++) {
        int k = aq + h*8;
        float4 v = *(const float4*)(Arow + k);
        if (MODE == 1) {
            float4 s = *(const float4*)(s1p + k);
            v.x += s.x + s2i; v.y += s.y + s2i; v.z += s.z + s2i; v.w += s.w + s2i;
        }
        ar[h*4]=v.x; ar[h*4+1]=v.y; ar[h*4+2]=v.z; ar[h*4+3]=v.w;
    }
    {
        const float* p = Bm + (size_t)(kbase + bk) * HH + n0 + bn;
        #pragma unroll
        for (int t = 0; t < 2; t++) {
            int n = n0 + bn + 2*t;
            float2 v = (n < HH) ? *(const float2*)(p + 2*t) : make_float2(0.f,0.f);
            br[2*t] = v.x; br[2*t+1] = v.y;
        }
    }

    for (int it = 0; it < 12; it++) {
        __syncthreads();
        #pragma unroll
        for (int h = 0; h < 2; h++)
            #pragma unroll
            for (int j = 0; j < 4; j++)
                As[aq + h*8 + j][arow] = ar[h*4 + j];
        #pragma unroll
        for (int j = 0; j < 4; j++) Bs[bk][bn + j] = br[j];
        __syncthreads();
        if (it + 1 < 12) {
            int k0 = (it + 1) * 16;
            #pragma unroll
            for (int h = 0; h < 2; h++) {
                int k = k0 + aq + h*8;
                float4 v = *(const float4*)(Arow + k);
                if (MODE == 1) {
                    float4 s = *(const float4*)(s1p + k);
                    v.x += s.x + s2i; v.y += s.y + s2i; v.z += s.z + s2i; v.w += s.w + s2i;
                }
                ar[h*4]=v.x; ar[h*4+1]=v.y; ar[h*4+2]=v.z; ar[h*4+3]=v.w;
            }
            const float* p = Bm + (size_t)(kbase + k0 + bk) * HH + n0 + bn;
            #pragma unroll
            for (int t = 0; t < 2; t++) {
                int n = n0 + bn + 2*t;
                float2 v = (n < HH) ? *(const float2*)(p + 2*t) : make_float2(0.f,0.f);
                br[2*t] = v.x; br[2*t+1] = v.y;
            }
        }
        #pragma unroll
        for (int kk = 0; kk < 16; kk++) {
            float4 a = *(const float4*)&As[kk][ty*4];
            float2 b0v = *(const float2*)&Bs[kk][tx*4];
            float2 b1v = *(const float2*)&Bs[kk][tx*4 + 2];
            float am[4] = {a.x,a.y,a.z,a.w};
            float wn[4] = {b0v.x,b0v.y,b1v.x,b1v.y};
            #pragma unroll
            for (int i = 0; i < 4; i++)
                #pragma unroll
                for (int j = 0; j < 4; j++)
                    acc[i][j] = fmaf(am[i], wn[j], acc[i][j]);
        }
    }

    #pragma unroll
    for (int i = 0; i < 4; i++) {
        int row = b*SSZ + m0 + ty*4 + i;
        #pragma unroll
        for (int j = 0; j < 4; j++) {
            int n = n0 + tx*4 + j;
            if (n < HH) Cp[(size_t)row*HH + n] = acc[i][j];
        }
    }
}

// ======= stage3: P += g0@W1b^T ; OX += g0@WoutA^T ; s1/s2 ===================
#define PAB 120
#define OAB 240
__global__ __launch_bounds__(128) void stage3(const float* __restrict__ W1,
                                              const float* __restrict__ Wout,
                                              const float* __restrict__ b0) {
    int bx = blockIdx.x;
    if (bx < PAB) {
        ntB<1>(nullptr, 0, HH, b0, W1 + DD, D1, HH, (bx/5)*64, (bx%5)*32,
               nullptr, g_P, g_P, HH);
        return;
    }
    if (bx < PAB + OAB) {
        int t = bx - PAB;
        ntB<1>(nullptr, 0, HH, b0, Wout, DD, DD, (t/10)*64, (t%10)*32,
               nullptr, g_OX, g_OX, DD);
        return;
    }
    // s1/s2: thread per row of g0 (recompute epilogue on load)
    __shared__ float sw1[HH], sw2[HH], sb0[HH];
    int tid = threadIdx.x;
    for (int i = tid; i < HH; i += 128) {
        sw1[i] = g_w1s[i]; sw2[i] = g_w2s[i]; sb0[i] = b0[i];
    }
    __syncthreads();
    int row = (bx - PAB - OAB) * 128 + tid;
    const float* pa = g_c0a + (size_t)row * HH;
    const float* pb = g_c0b + (size_t)row * HH;
    const float* pq = g_Q   + (size_t)row * HH;
    float a1 = 0.f, a2 = 0.f;
    for (int k = 0; k < HH; k += 2) {
        float2 a = *(const float2*)(pa + k);
        float2 b = *(const float2*)(pb + k);
        float2 q = *(const float2*)(pq + k);
        float gx = fmaxf(fmaf(a.x + b.x, INVE, q.x + 2.f*sb0[k]),   0.f);
        float gy = fmaxf(fmaf(a.y + b.y, INVE, q.y + 2.f*sb0[k+1]), 0.f);
        a1 = fmaf(gx, sw1[k], a1);  a1 = fmaf(gy, sw1[k+1], a1);
        a2 = fmaf(gx, sw2[k], a2);  a2 = fmaf(gy, sw2[k+1], a2);
    }
    g_s1[row] = a1;
    g_s2[row] = a2;
}

// ======= stage6: out = OX + g1@WoutB^T ======================================
__global__ __launch_bounds__(128) void stage6(const float* __restrict__ Wout,
                                              const float* __restrict__ b1,
                                              float* __restrict__ out) {
    int bx = blockIdx.x;
    ntB<2>(nullptr, 0, HH, b1, Wout + HH, DD, DD, (bx/10)*64, (bx%10)*32,
           nullptr, g_OX, out, DD);
}

// ======= launch =============================================================
extern "C" void kernel_launch(void* const* d_in, const int* in_sizes, int n_in,
                              void* d_out, int out_size) {
    const float* adj  = (const float*)d_in[0];
    const float* X    = (const float*)d_in[1];
    const float* W0   = (const float*)d_in[2];
    const float* b0   = (const float*)d_in[3];
    const float* W1   = (const float*)d_in[4];
    const float* b1   = (const float*)d_in[5];
    const float* Wh   = (const float*)d_in[6];
    const float* bh   = (const float*)d_in[7];
    const float* Wout = (const float*)d_in[8];
    const float* bout = (const float*)d_in[9];
    float* out = (float*)d_out;

    prep_weights<<<1, 256>>>(Wh, bh);

    // Q, PX, OX GEMMs overlapped with the 118MB adj streaming pass
    stage1<<<GEMMB + ADJ_BLOCKS, 128>>>(adj, X, W0, W1, Wout, bout);

    // split-K partials of A0@Q
    bat<0><<<dim3(5, 6, 8), 128>>>();

    // P += g0@W1b^T ; OX += g0@WoutA^T ; s1/s2   (g0 epilogue fused in loads)
    stage3<<<PAB + OAB + 12, 128>>>(W1, Wout, b0);

    // split-K partials of Atilde1@P
    bat<1><<<dim3(5, 6, 8), 128>>>();

    // out = OX + g1@WoutB^T   (g1 epilogue fused in loads)
    stage6<<<OAB, 128>>>(Wout, b1, out);
}